// round 10
// baseline (speedup 1.0000x reference)
#include <cuda_runtime.h>
#include <math.h>

#define N     16384
#define S     8192
#define T     1024
#define GPT   16
#define CELLS 512
#define R2    0.0625f
#define KNB   10

// Distance formula matching XLA's contraction of sum((a-b)**2, -1).
__device__ __forceinline__ float dist2(float dx, float dy, float dz) {
    return fmaf(dz, dz, fmaf(dy, dy, __fmul_rn(dx, dx)));
}

__device__ __forceinline__ int morton3(int x, int y, int z) {
    int m = 0;
#pragma unroll
    for (int b = 0; b < 3; ++b)
        m |= (((x >> b) & 1) << (3*b)) | (((y >> b) & 1) << (3*b + 1)) |
             (((z >> b) & 1) << (3*b + 2));
    return m;
}

// ---------------- global scratch ----------------
__device__ float g_xs[N], g_ys[N], g_zs[N];
__device__ int   g_s2o[N];
__device__ int   g_fps_idx[S];
__device__ int   g_src[S * KNB];

// ---------------- K0: counting sort into Morton-ordered 8x8x8 grid ----------------
__global__ __launch_bounds__(T, 1) void sort_kernel(const float* __restrict__ pos) {
    __shared__ int hist[CELLS];
    __shared__ int scanbuf[CELLS];
    int tid = threadIdx.x;
    if (tid < CELLS) hist[tid] = 0;
    __syncthreads();
#pragma unroll
    for (int g = 0; g < GPT; ++g) {
        int i = g * T + tid;
        float x = pos[3*i], y = pos[3*i+1], z = pos[3*i+2];
        int cx = min(7, (int)(x * 8.0f));
        int cy = min(7, (int)(y * 8.0f));
        int cz = min(7, (int)(z * 8.0f));
        atomicAdd(&hist[morton3(cx, cy, cz)], 1);
    }
    __syncthreads();
    if (tid < CELLS) scanbuf[tid] = hist[tid];
    __syncthreads();
    for (int off = 1; off < CELLS; off <<= 1) {
        int v = 0;
        if (tid < CELLS) { v = scanbuf[tid]; if (tid >= off) v += scanbuf[tid - off]; }
        __syncthreads();
        if (tid < CELLS) scanbuf[tid] = v;
        __syncthreads();
    }
    if (tid < CELLS) hist[tid] = scanbuf[tid] - hist[tid];
    __syncthreads();
#pragma unroll
    for (int g = 0; g < GPT; ++g) {
        int i = g * T + tid;
        float x = pos[3*i], y = pos[3*i+1], z = pos[3*i+2];
        int cx = min(7, (int)(x * 8.0f));
        int cy = min(7, (int)(y * 8.0f));
        int cz = min(7, (int)(z * 8.0f));
        int c  = morton3(cx, cy, cz);
        int d  = atomicAdd(&hist[c], 1);
        int a  = (d & 15) * T + (d >> 4);
        g_xs[a] = x; g_ys[a] = y; g_zs[a] = z;
        g_s2o[a] = i;
    }
}

// dummy kernels: position fps_kernel at launch index 3 so ncu captures it
__global__ void dummy_kernel() {}

// ---------------- K1: barrier-free pruned FPS (single block) ----------------
// Publish/poll sync: each warp publishes [tag:4|val:32|key:28] as one STS.64
// into sbest[t&1][wid]; all warps poll this parity's 32 slots until tags == t&15.
// Warp skew is provably <=1 step, so parity buffering + 4-bit tags are safe.
// Reduction semantics identical to R8 (bit-exact): max val, then max key
// (key = (~orig<<14)|layout  =>  lowest original index among ties).
__global__ __launch_bounds__(T, 1) void fps_kernel(const float* __restrict__ pos) {
    extern __shared__ float sm[];
    float2* sxy = (float2*)sm;        // 128KB
    float*  sz  = sm + 2 * N;         // 64KB
    __shared__ volatile unsigned long long sbest[2][32];
    int tid  = threadIdx.x;
    int lane = tid & 31;
    int wid  = tid >> 5;
    if (tid == 0) g_fps_idx[0] = 0;
    if (tid < 64) sbest[tid >> 5][tid & 31] = 0ull;   // tag 0 != first tags (1,2)

    unsigned pk[GPT/2];
#pragma unroll
    for (int g = 0; g < GPT/2; ++g) pk[g] = 0u;
#pragma unroll
    for (int g = 0; g < GPT; ++g) {
        int a = g * T + tid;
        sxy[a] = make_float2(g_xs[a], g_ys[a]);
        sz[a]  = g_zs[a];
        unsigned ko = (~(unsigned)g_s2o[a]) & 0x3FFFu;   // max(~orig) == min(orig)
        pk[g >> 1] |= ko << (16 * (g & 1));
    }
    __syncthreads();

    // group centroid + radius (upper bound, padded)
    float qx = 0.f, qy = 0.f, qz = 0.f;
#pragma unroll
    for (int g = 0; g < GPT; ++g) {
        int a = g * T + tid;
        float2 xy = sxy[a];
        qx += xy.x; qy += xy.y; qz += sz[a];
    }
    qx *= (1.0f / GPT); qy *= (1.0f / GPT); qz *= (1.0f / GPT);
    float rr = 0.f;
#pragma unroll
    for (int g = 0; g < GPT; ++g) {
        int a = g * T + tid;
        float2 xy = sxy[a];
        float dx = xy.x - qx, dy = xy.y - qy, dz = sz[a] - qz;
        rr = fmaxf(rr, dx*dx + dy*dy + dz*dz);
    }
    float r = sqrtf(rr) + 1e-4f;

    float m[GPT];
#pragma unroll
    for (int g = 0; g < GPT; ++g) m[g] = 3.402823466e38f;
    float    Mg   = 3.402823466e38f;
    unsigned kb   = 0u;
    unsigned ab   = (unsigned)tid;
    float    thr2 = 3.402823466e38f;   // force update at t=1
    unsigned wval = 0u, wk2 = 0u;      // warp best (set at t=1)

    float cx = pos[0], cy = pos[1], cz = pos[2];

    for (int t = 1; t < S; ++t) {
        int p = t & 1;
        unsigned tag = (unsigned)(t & 15);
        float dqx = qx - cx, dqy = qy - cy, dqz = qz - cz;
        float dd  = dqx*dqx + dqy*dqy + dqz*dqz;
        bool need = dd < thr2;
        unsigned upd = __ballot_sync(0xffffffffu, need);
        if (upd) {
            if (need) {
                float Ml = -1.0f; unsigned kbl = 0u, abl = 0u;
#pragma unroll
                for (int g = 0; g < GPT; ++g) {
                    int a = g * T + tid;
                    float2 xy = sxy[a];
                    float dx = __fsub_rn(xy.x, cx);
                    float dy = __fsub_rn(xy.y, cy);
                    float dz = __fsub_rn(sz[a], cz);
                    float d  = dist2(dx, dy, dz);
                    float nm = fminf(m[g], d);
                    m[g] = nm;
                    unsigned ko = (pk[g >> 1] >> (16 * (g & 1))) & 0xFFFFu;
                    if (nm > Ml)                   { Ml = nm; kbl = ko; abl = (unsigned)a; }
                    else if (nm == Ml && ko > kbl) {          kbl = ko; abl = (unsigned)a; }
                }
                Mg = Ml; kb = kbl; ab = abl;
                float thr = sqrtf(Mg) + r + 1e-3f;
                thr2 = thr * thr;
            }
            unsigned vb   = __float_as_uint(Mg);
            unsigned wmax = __reduce_max_sync(0xffffffffu, vb);
            wval = wmax;
            wk2  = __reduce_max_sync(0xffffffffu,
                                     (vb == wmax) ? ((kb << 14) | ab) : 0u);
        }
        // publish: single 8-byte store (tear-free), tag inside the word
        if (lane == 0)
            sbest[p][wid] = ((unsigned long long)tag << 60) |
                            ((unsigned long long)wval << 28) |
                            (unsigned long long)wk2;
        // poll this parity's 32 slots until every tag matches this step
        unsigned long long v;
        do {
            v = sbest[p][lane];
        } while (!__all_sync(0xffffffffu, (unsigned)(v >> 60) == tag));
        unsigned val  = (unsigned)(v >> 28);          // truncation keeps low 32 of val
        unsigned key  = (unsigned)v & 0xFFFFFFFu;
        unsigned gmax = __reduce_max_sync(0xffffffffu, val);
        unsigned gk2  = __reduce_max_sync(0xffffffffu, (val == gmax) ? key : 0u);
        int w = (int)(gk2 & 0x3FFFu);
        if (tid == 0) g_fps_idx[t] = (int)((~(gk2 >> 14)) & 0x3FFFu);
        float2 cxy = sxy[w];
        cx = cxy.x; cy = cxy.y; cz = sz[w];
    }
}

// ---------------- K2: top-10 nearest neighbors, 1 warp per center ----------------
__global__ __launch_bounds__(512, 1) void knn_kernel(const float* __restrict__ pos) {
    extern __shared__ float sp[];     // 3*N floats = 192KB
    int tid = threadIdx.x, lane = tid & 31, w = tid >> 5;
    const float4* p4 = (const float4*)pos;
    float4* s4 = (float4*)sp;
#pragma unroll
    for (int i = 0; i < (3 * N / 4) / 512; ++i)
        s4[i * 512 + tid] = p4[i * 512 + tid];
    __syncthreads();

    int c  = blockIdx.x * 16 + w;
    int fi = g_fps_idx[c];
    float cx = sp[3*fi], cy = sp[3*fi+1], cz = sp[3*fi+2];

    float bd[KNB]; int bi[KNB];
#pragma unroll
    for (int k = 0; k < KNB; ++k) { bd[k] = 3.402823466e38f; bi[k] = -1; }

    for (int j = 0; j < N / 32; ++j) {
        int p = j * 32 + lane;
        float dx = __fsub_rn(sp[3*p],     cx);
        float dy = __fsub_rn(sp[3*p + 1], cy);
        float dz = __fsub_rn(sp[3*p + 2], cz);
        float d  = dist2(dx, dy, dz);
        if (d < bd[KNB - 1]) {
            bd[KNB - 1] = d; bi[KNB - 1] = p;
#pragma unroll
            for (int k = KNB - 1; k > 0; --k) {
                if (bd[k] < bd[k - 1]) {
                    float td = bd[k]; bd[k] = bd[k-1]; bd[k-1] = td;
                    int   ti = bi[k]; bi[k] = bi[k-1]; bi[k-1] = ti;
                } else break;
            }
        }
    }

    int cur = 0;
    for (int o = 0; o < KNB; ++o) {
        float hd_f; int hp;
        {
            float fv = bd[0]; int iv = bi[0];
#pragma unroll
            for (int k = 1; k < KNB; ++k) { fv = (cur == k) ? bd[k] : fv; iv = (cur == k) ? bi[k] : iv; }
            hd_f = fv; hp = iv;
        }
        unsigned hd   = __float_as_uint(hd_f);
        unsigned dmin = __reduce_min_sync(0xffffffffu, hd);
        int cand = (hd == dmin) ? hp : 0x7FFFFFFF;
        int pmin = (int)__reduce_min_sync(0xffffffffu, (unsigned)cand);
        if (lane == 0)
            g_src[c * KNB + o] = (__uint_as_float(dmin) <= R2) ? pmin : -1;
        if (hd == dmin && hp == pmin) cur++;
    }
}

// ---------------- K3: MLP (3->64 relu ->128) + max over valid neighbors ----------------
__global__ __launch_bounds__(128, 4) void mlp_kernel(const float* __restrict__ pos,
                                                     const float* __restrict__ W1,
                                                     const float* __restrict__ b1,
                                                     const float* __restrict__ W2,
                                                     const float* __restrict__ b2,
                                                     float* __restrict__ out) {
    __shared__ float h1[2][64];
    __shared__ int   ssrc[KNB];
    int tid  = threadIdx.x;
    int half = tid >> 6;
    int hid  = tid & 63;
    float w2r[64];
#pragma unroll
    for (int k = 0; k < 64; ++k) w2r[k] = W2[k * 128 + tid];
    float b2t = b2[tid];
    float w1x = W1[hid], w1y = W1[64 + hid], w1z = W1[128 + hid], b1k = b1[hid];

    for (int ci = 0; ci < 8; ++ci) {
        int i = blockIdx.x * 8 + ci;
        __syncthreads();
        if (tid < KNB) ssrc[tid] = g_src[i * KNB + tid];
        float pix = pos[3*i], piy = pos[3*i+1], piz = pos[3*i+2];
        __syncthreads();
        int cnt = 0;
#pragma unroll
        for (int k = 0; k < KNB; ++k) cnt += (ssrc[k] >= 0);
        float mx = __int_as_float(0xff800000);
        for (int nb = 0; nb < cnt; nb += 2) {
            int mynb = nb + half;
            if (mynb < cnt) {
                int sp = ssrc[mynb];
                float rx = pos[3*sp]     - pix;
                float ry = pos[3*sp + 1] - piy;
                float rz = pos[3*sp + 2] - piz;
                float h = fmaf(rz, w1z, fmaf(ry, w1y, __fmul_rn(rx, w1x))) + b1k;
                h1[half][hid] = fmaxf(h, 0.0f);
            }
            __syncthreads();
            float acc = b2t;
#pragma unroll
            for (int k = 0; k < 64; ++k) acc = fmaf(h1[0][k], w2r[k], acc);
            mx = fmaxf(mx, acc);
            if (nb + 1 < cnt) {
                float acc1 = b2t;
#pragma unroll
                for (int k = 0; k < 64; ++k) acc1 = fmaf(h1[1][k], w2r[k], acc1);
                mx = fmaxf(mx, acc1);
            }
            __syncthreads();
        }
        out[i * 128 + tid] = (cnt > 0) ? mx : 0.0f;
    }
}

// ---------------- K4: zero tail rows [S, N) ----------------
__global__ void zero_tail_kernel(float* __restrict__ out) {
    int i = blockIdx.x * blockDim.x + threadIdx.x;
    float4* o = (float4*)(out + S * 128);
    o[i] = make_float4(0.f, 0.f, 0.f, 0.f);
}

extern "C" void kernel_launch(void* const* d_in, const int* in_sizes, int n_in,
                              void* d_out, int out_size) {
    const float* pos = (const float*)d_in[0];
    const float* W1 = (const float*)d_in[2];
    const float* b1 = (const float*)d_in[3];
    const float* W2 = (const float*)d_in[4];
    const float* b2 = (const float*)d_in[5];
    float* out = (float*)d_out;

    static bool attr_set = false;
    if (!attr_set) {
        cudaFuncSetAttribute(fps_kernel, cudaFuncAttributeMaxDynamicSharedMemorySize,
                             3 * N * (int)sizeof(float));
        cudaFuncSetAttribute(knn_kernel, cudaFuncAttributeMaxDynamicSharedMemorySize,
                             3 * N * (int)sizeof(float));
        attr_set = true;
    }

    sort_kernel<<<1, T>>>(pos);
    dummy_kernel<<<1, 32>>>();                 // pad launch indices so fps lands at
    dummy_kernel<<<1, 32>>>();                 // idx 3 (the slot ncu captures)
    fps_kernel<<<1, T, 3 * N * sizeof(float)>>>(pos);
    knn_kernel<<<S / 16, 512, 3 * N * sizeof(float)>>>(pos);
    mlp_kernel<<<S / 8, 128>>>(pos, W1, b1, W2, b2, out);
    zero_tail_kernel<<<(S * 128 / 4) / 256, 256>>>(out);
}

// round 12
// speedup vs baseline: 5.5839x; 5.5839x over previous
#include <cuda_runtime.h>
#include <math.h>

#define N     16384
#define S     8192
#define T     1024
#define GPT   16
#define CELLS 512
#define R2    0.0625f
#define KNB   10

// Distance formula matching XLA's contraction of sum((a-b)**2, -1).
__device__ __forceinline__ float dist2(float dx, float dy, float dz) {
    return fmaf(dz, dz, fmaf(dy, dy, __fmul_rn(dx, dx)));
}

__device__ __forceinline__ int morton3(int x, int y, int z) {
    int m = 0;
#pragma unroll
    for (int b = 0; b < 3; ++b)
        m |= (((x >> b) & 1) << (3*b)) | (((y >> b) & 1) << (3*b + 1)) |
             (((z >> b) & 1) << (3*b + 2));
    return m;
}

// ---------------- global scratch ----------------
__device__ float g_xs[N], g_ys[N], g_zs[N];
__device__ int   g_s2o[N];
__device__ int   g_fps_idx[S];
__device__ int   g_src[S * KNB];

// ---------------- K0: counting sort into Morton-ordered 8x8x8 grid ----------------
__global__ __launch_bounds__(T, 1) void sort_kernel(const float* __restrict__ pos) {
    __shared__ int hist[CELLS];
    __shared__ int scanbuf[CELLS];
    int tid = threadIdx.x;
    if (tid < CELLS) hist[tid] = 0;
    __syncthreads();
#pragma unroll
    for (int g = 0; g < GPT; ++g) {
        int i = g * T + tid;
        float x = pos[3*i], y = pos[3*i+1], z = pos[3*i+2];
        int cx = min(7, (int)(x * 8.0f));
        int cy = min(7, (int)(y * 8.0f));
        int cz = min(7, (int)(z * 8.0f));
        atomicAdd(&hist[morton3(cx, cy, cz)], 1);
    }
    __syncthreads();
    if (tid < CELLS) scanbuf[tid] = hist[tid];
    __syncthreads();
    for (int off = 1; off < CELLS; off <<= 1) {
        int v = 0;
        if (tid < CELLS) { v = scanbuf[tid]; if (tid >= off) v += scanbuf[tid - off]; }
        __syncthreads();
        if (tid < CELLS) scanbuf[tid] = v;
        __syncthreads();
    }
    if (tid < CELLS) hist[tid] = scanbuf[tid] - hist[tid];
    __syncthreads();
#pragma unroll
    for (int g = 0; g < GPT; ++g) {
        int i = g * T + tid;
        float x = pos[3*i], y = pos[3*i+1], z = pos[3*i+2];
        int cx = min(7, (int)(x * 8.0f));
        int cy = min(7, (int)(y * 8.0f));
        int cz = min(7, (int)(z * 8.0f));
        int c  = morton3(cx, cy, cz);
        int d  = atomicAdd(&hist[c], 1);
        int a  = (d & 15) * T + (d >> 4);
        g_xs[a] = x; g_ys[a] = y; g_zs[a] = z;
        g_s2o[a] = i;
    }
}

// dummy kernels: position fps_kernel at launch index 3 for ncu capture
__global__ void dummy_kernel() {}

// ---------------- K1: pruned FPS (single block, barrier-synced — R8 structure) ----------------
// One __syncthreads per step with parity double-buffered warp-best array.
// Tie-break = lowest original index via key (~orig<<14)|layout (bit-exact).
// Rescan tail uses a max TREE + predicated key selects (same semantics as the
// serial chain: max val, then max ~orig among value-ties; (val,ko) ties impossible).
__global__ __launch_bounds__(T, 1) void fps_kernel(const float* __restrict__ pos) {
    extern __shared__ float sm[];
    float2* sxy = (float2*)sm;        // 128KB
    float*  sz  = sm + 2 * N;         // 64KB
    __shared__ uint2 sbest[2][32];
    int tid  = threadIdx.x;
    int lane = tid & 31;
    int wid  = tid >> 5;
    if (tid == 0) g_fps_idx[0] = 0;

    unsigned pk[GPT/2];
#pragma unroll
    for (int g = 0; g < GPT/2; ++g) pk[g] = 0u;
#pragma unroll
    for (int g = 0; g < GPT; ++g) {
        int a = g * T + tid;
        sxy[a] = make_float2(g_xs[a], g_ys[a]);
        sz[a]  = g_zs[a];
        unsigned ko = (~(unsigned)g_s2o[a]) & 0x3FFFu;   // max(~orig) == min(orig)
        pk[g >> 1] |= ko << (16 * (g & 1));
    }
    __syncthreads();

    // group centroid + radius (upper bound, padded)
    float qx = 0.f, qy = 0.f, qz = 0.f;
#pragma unroll
    for (int g = 0; g < GPT; ++g) {
        int a = g * T + tid;
        float2 xy = sxy[a];
        qx += xy.x; qy += xy.y; qz += sz[a];
    }
    qx *= (1.0f / GPT); qy *= (1.0f / GPT); qz *= (1.0f / GPT);
    float rr = 0.f;
#pragma unroll
    for (int g = 0; g < GPT; ++g) {
        int a = g * T + tid;
        float2 xy = sxy[a];
        float dx = xy.x - qx, dy = xy.y - qy, dz = sz[a] - qz;
        rr = fmaxf(rr, dx*dx + dy*dy + dz*dz);
    }
    float r = sqrtf(rr) + 1e-4f;

    float m[GPT];
#pragma unroll
    for (int g = 0; g < GPT; ++g) m[g] = 3.402823466e38f;
    float    Mg   = 3.402823466e38f;
    unsigned kb   = 0u;                 // ko of lane argmax
    unsigned ab   = (unsigned)tid;      // layout addr of lane argmax
    float    thr2 = 3.402823466e38f;    // force update at t=1
    unsigned wval = 0u, wk2 = 0u;       // warp best (set at t=1)

    float cx = pos[0], cy = pos[1], cz = pos[2];

    for (int t = 1; t < S; ++t) {
        int p = t & 1;
        float dqx = qx - cx, dqy = qy - cy, dqz = qz - cz;
        float dd  = dqx*dqx + dqy*dqy + dqz*dqz;
        bool need = dd < thr2;
        unsigned upd = __ballot_sync(0xffffffffu, need);
        if (upd) {
            if (need) {
                float nm[GPT];
#pragma unroll
                for (int g = 0; g < GPT; ++g) {
                    int a = g * T + tid;
                    float2 xy = sxy[a];
                    float dx = __fsub_rn(xy.x, cx);
                    float dy = __fsub_rn(xy.y, cy);
                    float dz = __fsub_rn(sz[a], cz);
                    float d  = dist2(dx, dy, dz);
                    nm[g] = fminf(m[g], d);
                    m[g]  = nm[g];
                }
                // max tree over the 16 independent nm values (depth 4)
                float t8[8], t4[4], t2[2];
#pragma unroll
                for (int j = 0; j < 8; ++j) t8[j] = fmaxf(nm[j], nm[j + 8]);
#pragma unroll
                for (int j = 0; j < 4; ++j) t4[j] = fmaxf(t8[j], t8[j + 4]);
                t2[0] = fmaxf(t4[0], t4[2]); t2[1] = fmaxf(t4[1], t4[3]);
                float Ml = fmaxf(t2[0], t2[1]);
                // among nm[g] == Ml pick max packed key (ko<<14)|a == max ko
                unsigned kab = 0u;
#pragma unroll
                for (int g = 0; g < GPT; ++g) {
                    unsigned ko = (pk[g >> 1] >> (16 * (g & 1))) & 0xFFFFu;
                    unsigned cand = (ko << 14) | (unsigned)(g * T + tid);
                    if (nm[g] == Ml && cand > kab) kab = cand;
                }
                Mg = Ml; kb = kab >> 14; ab = kab & 0x3FFFu;
                float thr = sqrtf(Mg) + r + 1e-3f;
                thr2 = thr * thr;
            }
            unsigned vb   = __float_as_uint(Mg);
            unsigned wmax = __reduce_max_sync(0xffffffffu, vb);
            wval = wmax;
            wk2  = __reduce_max_sync(0xffffffffu,
                                     (vb == wmax) ? ((kb << 14) | ab) : 0u);
        }
        if (lane == 0) sbest[p][wid] = make_uint2(wval, wk2);
        __syncthreads();
        uint2    b    = sbest[p][lane];
        unsigned gmax = __reduce_max_sync(0xffffffffu, b.x);
        unsigned gk2  = __reduce_max_sync(0xffffffffu, (b.x == gmax) ? b.y : 0u);
        int w = (int)(gk2 & 0x3FFFu);
        if (tid == 0) g_fps_idx[t] = (int)((~(gk2 >> 14)) & 0x3FFFu);
        float2 cxy = sxy[w];
        cx = cxy.x; cy = cxy.y; cz = sz[w];
    }
}

// ---------------- K2: top-10 nearest neighbors, 1 warp per center ----------------
__global__ __launch_bounds__(512, 1) void knn_kernel(const float* __restrict__ pos) {
    extern __shared__ float sp[];     // 3*N floats = 192KB
    int tid = threadIdx.x, lane = tid & 31, w = tid >> 5;
    const float4* p4 = (const float4*)pos;
    float4* s4 = (float4*)sp;
#pragma unroll
    for (int i = 0; i < (3 * N / 4) / 512; ++i)
        s4[i * 512 + tid] = p4[i * 512 + tid];
    __syncthreads();

    int c  = blockIdx.x * 16 + w;
    int fi = g_fps_idx[c];
    float cx = sp[3*fi], cy = sp[3*fi+1], cz = sp[3*fi+2];

    float bd[KNB]; int bi[KNB];
#pragma unroll
    for (int k = 0; k < KNB; ++k) { bd[k] = 3.402823466e38f; bi[k] = -1; }

    for (int j = 0; j < N / 32; ++j) {
        int p = j * 32 + lane;
        float dx = __fsub_rn(sp[3*p],     cx);
        float dy = __fsub_rn(sp[3*p + 1], cy);
        float dz = __fsub_rn(sp[3*p + 2], cz);
        float d  = dist2(dx, dy, dz);
        if (d < bd[KNB - 1]) {
            bd[KNB - 1] = d; bi[KNB - 1] = p;
#pragma unroll
            for (int k = KNB - 1; k > 0; --k) {
                if (bd[k] < bd[k - 1]) {
                    float td = bd[k]; bd[k] = bd[k-1]; bd[k-1] = td;
                    int   ti = bi[k]; bi[k] = bi[k-1]; bi[k-1] = ti;
                } else break;
            }
        }
    }

    int cur = 0;
    for (int o = 0; o < KNB; ++o) {
        float hd_f; int hp;
        {
            float fv = bd[0]; int iv = bi[0];
#pragma unroll
            for (int k = 1; k < KNB; ++k) { fv = (cur == k) ? bd[k] : fv; iv = (cur == k) ? bi[k] : iv; }
            hd_f = fv; hp = iv;
        }
        unsigned hd   = __float_as_uint(hd_f);
        unsigned dmin = __reduce_min_sync(0xffffffffu, hd);
        int cand = (hd == dmin) ? hp : 0x7FFFFFFF;
        int pmin = (int)__reduce_min_sync(0xffffffffu, (unsigned)cand);
        if (lane == 0)
            g_src[c * KNB + o] = (__uint_as_float(dmin) <= R2) ? pmin : -1;
        if (hd == dmin && hp == pmin) cur++;
    }
}

// ---------------- K3: MLP (3->64 relu ->128) + max over valid neighbors ----------------
__global__ __launch_bounds__(128, 4) void mlp_kernel(const float* __restrict__ pos,
                                                     const float* __restrict__ W1,
                                                     const float* __restrict__ b1,
                                                     const float* __restrict__ W2,
                                                     const float* __restrict__ b2,
                                                     float* __restrict__ out) {
    __shared__ float h1[2][64];
    __shared__ int   ssrc[KNB];
    int tid  = threadIdx.x;
    int half = tid >> 6;
    int hid  = tid & 63;
    float w2r[64];
#pragma unroll
    for (int k = 0; k < 64; ++k) w2r[k] = W2[k * 128 + tid];
    float b2t = b2[tid];
    float w1x = W1[hid], w1y = W1[64 + hid], w1z = W1[128 + hid], b1k = b1[hid];

    for (int ci = 0; ci < 8; ++ci) {
        int i = blockIdx.x * 8 + ci;
        __syncthreads();
        if (tid < KNB) ssrc[tid] = g_src[i * KNB + tid];
        float pix = pos[3*i], piy = pos[3*i+1], piz = pos[3*i+2];
        __syncthreads();
        int cnt = 0;
#pragma unroll
        for (int k = 0; k < KNB; ++k) cnt += (ssrc[k] >= 0);
        float mx = __int_as_float(0xff800000);
        for (int nb = 0; nb < cnt; nb += 2) {
            int mynb = nb + half;
            if (mynb < cnt) {
                int sp = ssrc[mynb];
                float rx = pos[3*sp]     - pix;
                float ry = pos[3*sp + 1] - piy;
                float rz = pos[3*sp + 2] - piz;
                float h = fmaf(rz, w1z, fmaf(ry, w1y, __fmul_rn(rx, w1x))) + b1k;
                h1[half][hid] = fmaxf(h, 0.0f);
            }
            __syncthreads();
            float acc = b2t;
#pragma unroll
            for (int k = 0; k < 64; ++k) acc = fmaf(h1[0][k], w2r[k], acc);
            mx = fmaxf(mx, acc);
            if (nb + 1 < cnt) {
                float acc1 = b2t;
#pragma unroll
                for (int k = 0; k < 64; ++k) acc1 = fmaf(h1[1][k], w2r[k], acc1);
                mx = fmaxf(mx, acc1);
            }
            __syncthreads();
        }
        out[i * 128 + tid] = (cnt > 0) ? mx : 0.0f;
    }
}

// ---------------- K4: zero tail rows [S, N) ----------------
__global__ void zero_tail_kernel(float* __restrict__ out) {
    int i = blockIdx.x * blockDim.x + threadIdx.x;
    float4* o = (float4*)(out + S * 128);
    o[i] = make_float4(0.f, 0.f, 0.f, 0.f);
}

extern "C" void kernel_launch(void* const* d_in, const int* in_sizes, int n_in,
                              void* d_out, int out_size) {
    const float* pos = (const float*)d_in[0];
    const float* W1 = (const float*)d_in[2];
    const float* b1 = (const float*)d_in[3];
    const float* W2 = (const float*)d_in[4];
    const float* b2 = (const float*)d_in[5];
    float* out = (float*)d_out;

    static bool attr_set = false;
    if (!attr_set) {
        cudaFuncSetAttribute(fps_kernel, cudaFuncAttributeMaxDynamicSharedMemorySize,
                             3 * N * (int)sizeof(float));
        cudaFuncSetAttribute(knn_kernel, cudaFuncAttributeMaxDynamicSharedMemorySize,
                             3 * N * (int)sizeof(float));
        attr_set = true;
    }

    sort_kernel<<<1, T>>>(pos);
    dummy_kernel<<<1, 32>>>();                 // pad launch indices so fps lands at
    dummy_kernel<<<1, 32>>>();                 // the slot ncu captures
    fps_kernel<<<1, T, 3 * N * sizeof(float)>>>(pos);
    knn_kernel<<<S / 16, 512, 3 * N * sizeof(float)>>>(pos);
    mlp_kernel<<<S / 8, 128>>>(pos, W1, b1, W2, b2, out);
    zero_tail_kernel<<<(S * 128 / 4) / 256, 256>>>(out);
}